// round 8
// baseline (speedup 1.0000x reference)
#include <cuda_runtime.h>
#include <cuda_fp16.h>
#include <cstdint>

// Edge-MLP, factored:
//   H[n] = [ x[n]@W1[0:128] + b1 | x[n]@W1[128:256] ]   (node GEMM, tensor cores)
//   out[e] = sigmoid( relu(H[r][0:64] + H[c][64:128]) . W2 + b2 )
// GEMM: fp16 2-term split, mma.sync m16n8k16, reg double-buffer, 2 CTAs/SM.
// Edge: 8 thr/edge, 2 edges/group, packed f32x2 FMA, 6 blocks/SM (48 warps).

#define NODE_DIM 128
#define HID      64
#define HOUT     128
#define MAXN     50176

__device__ __half g_H2[(size_t)MAXN * HOUT];

// ---------------- GEMM kernel (tile 128 x 128, K = 128) ----------------
#define GPITCH 272
#define SA_HI  0
#define SA_LO  34816
#define SB     69632
#define SMEM_G 104448

__device__ __forceinline__ uint32_t smem_u32(const void* p) {
    uint32_t a;
    asm("{ .reg .u64 t; cvta.to.shared.u64 t, %1; cvt.u32.u64 %0, t; }"
        : "=r"(a) : "l"(p));
    return a;
}
__device__ __forceinline__ void ldsm_x4(uint32_t* r, uint32_t a) {
    asm volatile("ldmatrix.sync.aligned.m8n8.x4.shared.b16 {%0,%1,%2,%3}, [%4];"
                 : "=r"(r[0]), "=r"(r[1]), "=r"(r[2]), "=r"(r[3]) : "r"(a));
}
__device__ __forceinline__ void ldsm_x2t(uint32_t* r, uint32_t a) {
    asm volatile("ldmatrix.sync.aligned.m8n8.x2.trans.shared.b16 {%0,%1}, [%2];"
                 : "=r"(r[0]), "=r"(r[1]) : "r"(a));
}
__device__ __forceinline__ void mma16816h(float* d, const uint32_t* a,
                                          const uint32_t* b) {
    asm volatile(
        "mma.sync.aligned.m16n8k16.row.col.f32.f16.f16.f32 "
        "{%0,%1,%2,%3},{%4,%5,%6,%7},{%8,%9},{%0,%1,%2,%3};"
        : "+f"(d[0]), "+f"(d[1]), "+f"(d[2]), "+f"(d[3])
        : "r"(a[0]), "r"(a[1]), "r"(a[2]), "r"(a[3]), "r"(b[0]), "r"(b[1]));
}
__device__ __forceinline__ uint32_t pack_hi_h(float a, float b, uint32_t& lo) {
    __half ha = __float2half_rn(a), hb = __float2half_rn(b);
    __half la = __float2half_rn(a - __half2float(ha));
    __half lb = __float2half_rn(b - __half2float(hb));
    __half2 h = __halves2half2(ha, hb);
    __half2 l = __halves2half2(la, lb);
    lo = *reinterpret_cast<uint32_t*>(&l);
    return *reinterpret_cast<uint32_t*>(&h);
}

__global__ __launch_bounds__(256, 2)
void node_gemm(const float* __restrict__ x,
               const float* __restrict__ W1,
               const float* __restrict__ b1,
               int n_nodes, int ntiles) {
    extern __shared__ char sm[];
    const uint32_t smb = smem_u32(sm);
    const int tid = threadIdx.x, lane = tid & 31, wid = tid >> 5;
    const int wm = wid & 3, wn = wid >> 2;

    for (int idx = tid; idx < NODE_DIM * HOUT; idx += 256) {
        int kk = idx >> 7, jj = idx & 127;
        float v = (jj < HID) ? W1[kk * HID + jj]
                             : W1[(NODE_DIM + kk) * HID + (jj - HID)];
        *reinterpret_cast<__half*>(sm + SB + kk * GPITCH + jj * 2) =
            __float2half_rn(v);
    }

    const uint32_t aoff = (uint32_t)(lane & 15) * GPITCH + (uint32_t)(lane >> 4) * 16;
    const uint32_t boff = (uint32_t)(lane & 15) * GPITCH;
    const int r_loc = tid >> 1, seg = tid & 1;

    int t = blockIdx.x;
    bool have = t < ntiles;
    if (have) {
        int rr = t * 128 + r_loc; if (rr >= n_nodes) rr = n_nodes - 1;
        const float4* src =
            reinterpret_cast<const float4*>(x + (size_t)rr * NODE_DIM) + seg * 16;
        char* dh = sm + SA_HI + r_loc * GPITCH + seg * 128;
        char* dl = sm + SA_LO + r_loc * GPITCH + seg * 128;
        #pragma unroll
        for (int i = 0; i < 16; i++) {
            float4 v = src[i];
            uint32_t l0, l1;
            uint32_t h0 = pack_hi_h(v.x, v.y, l0);
            uint32_t h1 = pack_hi_h(v.z, v.w, l1);
            *reinterpret_cast<uint2*>(dh + i * 8) = make_uint2(h0, h1);
            *reinterpret_cast<uint2*>(dl + i * 8) = make_uint2(l0, l1);
        }
    }

    while (have) {
        const int tn = t + (int)gridDim.x;
        const bool haveN = tn < ntiles;
        __syncthreads();

        float4 v[16];
        if (haveN) {
            int rr = tn * 128 + r_loc; if (rr >= n_nodes) rr = n_nodes - 1;
            const float4* src =
                reinterpret_cast<const float4*>(x + (size_t)rr * NODE_DIM) +
                seg * 16;
            #pragma unroll
            for (int i = 0; i < 16; i++) v[i] = src[i];
        }

        float d[2][8][4];
        #pragma unroll
        for (int mi = 0; mi < 2; mi++)
            #pragma unroll
            for (int ni = 0; ni < 8; ni++)
                #pragma unroll
                for (int q = 0; q < 4; q++) d[mi][ni][q] = 0.0f;

        const uint32_t aHi = smb + SA_HI + wm * 32 * GPITCH;
        const uint32_t aLo = smb + SA_LO + wm * 32 * GPITCH;
        const uint32_t bB  = smb + SB + wn * 64 * 2;
        #pragma unroll
        for (int ks = 0; ks < 8; ks++) {
            uint32_t ah[2][4], al[2][4];
            #pragma unroll
            for (int mi = 0; mi < 2; mi++) {
                uint32_t ao = mi * 16 * GPITCH + ks * 32 + aoff;
                ldsm_x4(ah[mi], aHi + ao);
                ldsm_x4(al[mi], aLo + ao);
            }
            #pragma unroll
            for (int ni = 0; ni < 8; ni++) {
                uint32_t bh[2];
                ldsm_x2t(bh, bB + ks * 16 * GPITCH + boff + ni * 16);
                #pragma unroll
                for (int mi = 0; mi < 2; mi++) {
                    mma16816h(d[mi][ni], ah[mi], bh);
                    mma16816h(d[mi][ni], al[mi], bh);
                }
            }
        }
        __syncthreads();

        if (haveN) {
            char* dh = sm + SA_HI + r_loc * GPITCH + seg * 128;
            char* dl = sm + SA_LO + r_loc * GPITCH + seg * 128;
            #pragma unroll
            for (int i = 0; i < 16; i++) {
                uint32_t l0, l1;
                uint32_t h0 = pack_hi_h(v[i].x, v[i].y, l0);
                uint32_t h1 = pack_hi_h(v[i].z, v[i].w, l1);
                *reinterpret_cast<uint2*>(dh + i * 8) = make_uint2(h0, h1);
                *reinterpret_cast<uint2*>(dl + i * 8) = make_uint2(l0, l1);
            }
        }

        const int m0 = t * 128;
        #pragma unroll
        for (int mi = 0; mi < 2; mi++) {
            int mA = m0 + wm * 32 + mi * 16 + (lane >> 2);
            #pragma unroll
            for (int ni = 0; ni < 8; ni++) {
                int c = wn * 64 + ni * 8 + (lane & 3) * 2;
                float d0 = d[mi][ni][0], d1 = d[mi][ni][1];
                float d2 = d[mi][ni][2], d3 = d[mi][ni][3];
                if (wn == 0) {
                    float2 bb = *reinterpret_cast<const float2*>(b1 + c);
                    d0 += bb.x; d1 += bb.y; d2 += bb.x; d3 += bb.y;
                }
                if (mA < n_nodes)
                    *reinterpret_cast<__half2*>(g_H2 + (size_t)mA * HOUT + c) =
                        __floats2half2_rn(d0, d1);
                if (mA + 8 < n_nodes)
                    *reinterpret_cast<__half2*>(g_H2 + (size_t)(mA + 8) * HOUT + c) =
                        __floats2half2_rn(d2, d3);
            }
        }
        t = tn; have = haveN;
    }
}

// -------- edge kernel: 8 thr/edge, 2 edges per group, high occupancy --------
__device__ __forceinline__ unsigned long long packf2(float a, float b) {
    unsigned long long r;
    asm("mov.b64 %0, {%1, %2};" : "=l"(r)
        : "r"(__float_as_uint(a)), "r"(__float_as_uint(b)));
    return r;
}
__device__ __forceinline__ void fma2p(unsigned long long& d,
                                      unsigned long long a,
                                      unsigned long long b) {
    asm("fma.rn.f32x2 %0, %1, %2, %0;" : "+l"(d) : "l"(a), "l"(b));
}

__global__ __launch_bounds__(256, 6)
void edge_eval(const int* __restrict__ ei,
               const float* __restrict__ W2,
               const float* __restrict__ b2,
               float* __restrict__ out,
               int E) {
    const int tid = threadIdx.x, lane = tid & 31, wid = tid >> 5;
    const int sub = lane & 7;          // 8-col slice [sub*8, +8)
    const int grp = lane >> 3;         // group 0..3 in warp, 2 edges each

    unsigned long long w2p[4];
    #pragma unroll
    for (int q = 0; q < 4; q++)
        w2p[q] = packf2(__ldg(W2 + sub * 8 + 2 * q),
                        __ldg(W2 + sub * 8 + 2 * q + 1));
    const float bias2 = __ldg(b2);

    const int stride = gridDim.x * 64;
    for (int eb = blockIdx.x * 64 + wid * 8 + grp * 2; eb < E; eb += stride) {
        int2 rv, cv;
        if (eb + 2 <= E) {
            rv = __ldg(reinterpret_cast<const int2*>(ei + eb));
            cv = __ldg(reinterpret_cast<const int2*>(ei + E + eb));
        } else {
            rv.x = rv.y = __ldg(ei + eb);
            cv.x = cv.y = __ldg(ei + E + eb);
        }
        const int rp[2] = {rv.x, rv.y};
        const int cp[2] = {cv.x, cv.y};

        uint4 av[2], bv[2];
        #pragma unroll
        for (int j = 0; j < 2; j++) {
            av[j] = __ldg(reinterpret_cast<const uint4*>(
                        g_H2 + (size_t)rp[j] * HOUT) + sub);
            bv[j] = __ldg(reinterpret_cast<const uint4*>(
                        g_H2 + (size_t)cp[j] * HOUT + HID) + sub);
        }

        float z[2];
        #pragma unroll
        for (int j = 0; j < 2; j++) {
            const __half2* ah = reinterpret_cast<const __half2*>(&av[j]);
            const __half2* bh = reinterpret_cast<const __half2*>(&bv[j]);
            unsigned long long z2 = 0;
            #pragma unroll
            for (int q = 0; q < 4; q++) {
                __half2 s = __hmax2(__hadd2(ah[q], bh[q]),
                                    __half2(__half(0), __half(0)));
                float2 f = __half22float2(s);
                fma2p(z2, packf2(f.x, f.y), w2p[q]);
            }
            uint32_t zl, zh;
            asm("mov.b64 {%0, %1}, %2;" : "=r"(zl), "=r"(zh) : "l"(z2));
            z[j] = __uint_as_float(zl) + __uint_as_float(zh);
        }
        #pragma unroll
        for (int j = 0; j < 2; j++) {
            z[j] += __shfl_xor_sync(0xFFFFFFFF, z[j], 1);
            z[j] += __shfl_xor_sync(0xFFFFFFFF, z[j], 2);
            z[j] += __shfl_xor_sync(0xFFFFFFFF, z[j], 4);
        }
        if (sub == 0) {
            #pragma unroll
            for (int j = 0; j < 2; j++) {
                if (eb + j < E)
                    out[eb + j] = 1.0f / (1.0f + __expf(-(z[j] + bias2)));
            }
        }
    }
}

extern "C" void kernel_launch(void* const* d_in, const int* in_sizes, int n_in,
                              void* d_out, int out_size) {
    const float* x  = (const float*)d_in[0];
    const int*   ei = (const int*)  d_in[1];
    const float* W1 = (const float*)d_in[2];
    const float* b1 = (const float*)d_in[3];
    const float* W2 = (const float*)d_in[4];
    const float* b2 = (const float*)d_in[5];
    float* out = (float*)d_out;

    const int E = out_size;
    int n_nodes = in_sizes[0] / NODE_DIM;
    if (n_nodes > MAXN) n_nodes = MAXN;
    const int ntiles = (n_nodes + 127) / 128;

    cudaFuncSetAttribute(node_gemm,
                         cudaFuncAttributeMaxDynamicSharedMemorySize, SMEM_G);

    int g1 = ntiles < 296 ? ntiles : 296;
    node_gemm<<<g1, 256, SMEM_G>>>(x, W1, b1, n_nodes, ntiles);

    edge_eval<<<888, 256>>>(ei, W2, b2, out, E);
}

// round 9
// speedup vs baseline: 1.1428x; 1.1428x over previous
#include <cuda_runtime.h>
#include <cuda_fp16.h>
#include <cstdint>

// Edge-MLP, factored:
//   H[n] = [ x[n]@W1[0:128] + b1 | x[n]@W1[128:256] ]   (node GEMM, tensor cores)
//   out[e] = sigmoid( relu(H[r][0:64] + H[c][64:128]) . W2 + b2 )
// GEMM: single-term fp16 mma.sync m16n8k16 (A and B fp16), reg double-buffer.
// H fp16, b1 folded. Edge kernel: 8 thr/edge, 4 edges/group (R7-proven config).

#define NODE_DIM 128
#define HID      64
#define HOUT     128
#define MAXN     50176

__device__ __half g_H2[(size_t)MAXN * HOUT];

// ---------------- GEMM kernel (tile 128 x 128, K = 128) ----------------
#define GPITCH 272           // 136 halfs per row — conflict-free ldmatrix
#define SA     0
#define SB     34816
#define SMEM_G 69632

__device__ __forceinline__ uint32_t smem_u32(const void* p) {
    uint32_t a;
    asm("{ .reg .u64 t; cvta.to.shared.u64 t, %1; cvt.u32.u64 %0, t; }"
        : "=r"(a) : "l"(p));
    return a;
}
__device__ __forceinline__ void ldsm_x4(uint32_t* r, uint32_t a) {
    asm volatile("ldmatrix.sync.aligned.m8n8.x4.shared.b16 {%0,%1,%2,%3}, [%4];"
                 : "=r"(r[0]), "=r"(r[1]), "=r"(r[2]), "=r"(r[3]) : "r"(a));
}
__device__ __forceinline__ void ldsm_x2t(uint32_t* r, uint32_t a) {
    asm volatile("ldmatrix.sync.aligned.m8n8.x2.trans.shared.b16 {%0,%1}, [%2];"
                 : "=r"(r[0]), "=r"(r[1]) : "r"(a));
}
__device__ __forceinline__ void mma16816h(float* d, const uint32_t* a,
                                          const uint32_t* b) {
    asm volatile(
        "mma.sync.aligned.m16n8k16.row.col.f32.f16.f16.f32 "
        "{%0,%1,%2,%3},{%4,%5,%6,%7},{%8,%9},{%0,%1,%2,%3};"
        : "+f"(d[0]), "+f"(d[1]), "+f"(d[2]), "+f"(d[3])
        : "r"(a[0]), "r"(a[1]), "r"(a[2]), "r"(a[3]), "r"(b[0]), "r"(b[1]));
}

__global__ __launch_bounds__(256, 1)
void node_gemm(const float* __restrict__ x,
               const float* __restrict__ W1,
               const float* __restrict__ b1,
               int n_nodes, int ntiles) {
    extern __shared__ char sm[];
    const uint32_t smb = smem_u32(sm);
    const int tid = threadIdx.x, lane = tid & 31, wid = tid >> 5;
    const int wm = wid & 3, wn = wid >> 2;   // warp: 32 rows x 64 cols

    // stage B[k][j] = (j<64 ? W1[k][j] : W1[128+k][j-64]) as fp16
    for (int idx = tid; idx < NODE_DIM * HOUT; idx += 256) {
        int kk = idx >> 7, jj = idx & 127;
        float v = (jj < HID) ? W1[kk * HID + jj]
                             : W1[(NODE_DIM + kk) * HID + (jj - HID)];
        *reinterpret_cast<__half*>(sm + SB + kk * GPITCH + jj * 2) =
            __float2half_rn(v);
    }

    const uint32_t aoff = (uint32_t)(lane & 15) * GPITCH + (uint32_t)(lane >> 4) * 16;
    const uint32_t boff = (uint32_t)(lane & 15) * GPITCH;
    const int r_loc = tid >> 1, seg = tid & 1;

    int t = blockIdx.x;
    bool have = t < ntiles;
    if (have) {
        int rr = t * 128 + r_loc; if (rr >= n_nodes) rr = n_nodes - 1;
        const float4* src =
            reinterpret_cast<const float4*>(x + (size_t)rr * NODE_DIM) + seg * 16;
        char* dh = sm + SA + r_loc * GPITCH + seg * 128;
        #pragma unroll
        for (int i = 0; i < 16; i++) {
            float4 v = src[i];
            *reinterpret_cast<uint2*>(dh + i * 8) = make_uint2(
                *(uint32_t*)&(__half2&)*(__half2[]){__floats2half2_rn(v.x, v.y)},
                *(uint32_t*)&(__half2&)*(__half2[]){__floats2half2_rn(v.z, v.w)});
        }
    }

    while (have) {
        const int tn = t + (int)gridDim.x;
        const bool haveN = tn < ntiles;
        __syncthreads();                 // current tile staged & visible

        // prefetch next tile's A rows into registers (hides under MMA)
        float4 v[16];
        if (haveN) {
            int rr = tn * 128 + r_loc; if (rr >= n_nodes) rr = n_nodes - 1;
            const float4* src =
                reinterpret_cast<const float4*>(x + (size_t)rr * NODE_DIM) +
                seg * 16;
            #pragma unroll
            for (int i = 0; i < 16; i++) v[i] = src[i];
        }

        // ---- MMA: 8 ksteps, warp tile 32x64, single fp16 term ----
        float d[2][8][4];
        #pragma unroll
        for (int mi = 0; mi < 2; mi++)
            #pragma unroll
            for (int ni = 0; ni < 8; ni++)
                #pragma unroll
                for (int q = 0; q < 4; q++) d[mi][ni][q] = 0.0f;

        const uint32_t aA = smb + SA + wm * 32 * GPITCH;
        const uint32_t bB = smb + SB + wn * 64 * 2;
        #pragma unroll
        for (int ks = 0; ks < 8; ks++) {
            uint32_t ah[2][4];
            #pragma unroll
            for (int mi = 0; mi < 2; mi++)
                ldsm_x4(ah[mi], aA + mi * 16 * GPITCH + ks * 32 + aoff);
            #pragma unroll
            for (int ni = 0; ni < 8; ni++) {
                uint32_t bh[2];
                ldsm_x2t(bh, bB + ks * 16 * GPITCH + boff + ni * 16);
                #pragma unroll
                for (int mi = 0; mi < 2; mi++)
                    mma16816h(d[mi][ni], ah[mi], bh);
            }
        }
        __syncthreads();                 // all warps done reading smem

        // store prefetched tile into smem
        if (haveN) {
            char* dh = sm + SA + r_loc * GPITCH + seg * 128;
            #pragma unroll
            for (int i = 0; i < 16; i++) {
                __half2 h0 = __floats2half2_rn(v[i].x, v[i].y);
                __half2 h1 = __floats2half2_rn(v[i].z, v[i].w);
                *reinterpret_cast<uint2*>(dh + i * 8) = make_uint2(
                    *reinterpret_cast<uint32_t*>(&h0),
                    *reinterpret_cast<uint32_t*>(&h1));
            }
        }

        // ---- epilogue: (+ b1 on first half), write H tile as fp16 ----
        const int m0 = t * 128;
        #pragma unroll
        for (int mi = 0; mi < 2; mi++) {
            int mA = m0 + wm * 32 + mi * 16 + (lane >> 2);
            #pragma unroll
            for (int ni = 0; ni < 8; ni++) {
                int c = wn * 64 + ni * 8 + (lane & 3) * 2;
                float d0 = d[mi][ni][0], d1 = d[mi][ni][1];
                float d2 = d[mi][ni][2], d3 = d[mi][ni][3];
                if (wn == 0) {
                    float2 bb = *reinterpret_cast<const float2*>(b1 + c);
                    d0 += bb.x; d1 += bb.y; d2 += bb.x; d3 += bb.y;
                }
                if (mA < n_nodes)
                    *reinterpret_cast<__half2*>(g_H2 + (size_t)mA * HOUT + c) =
                        __floats2half2_rn(d0, d1);
                if (mA + 8 < n_nodes)
                    *reinterpret_cast<__half2*>(g_H2 + (size_t)(mA + 8) * HOUT + c) =
                        __floats2half2_rn(d2, d3);
            }
        }
        t = tn; have = haveN;
    }
}

// -------- edge kernel: 8 threads/edge, 4 edges per group (R7 config) --------
__global__ __launch_bounds__(256, 4)
void edge_eval(const int* __restrict__ ei,
               const float* __restrict__ W2,
               const float* __restrict__ b2,
               float* __restrict__ out,
               int E) {
    const int tid = threadIdx.x, lane = tid & 31, wid = tid >> 5;
    const int sub = lane & 7;
    const int grp = lane >> 3;

    float w2r[8];
    #pragma unroll
    for (int i = 0; i < 8; i++) w2r[i] = __ldg(W2 + sub * 8 + i);
    const float bias2 = __ldg(b2);

    const int stride = gridDim.x * 128;
    for (int eb = blockIdx.x * 128 + wid * 16 + grp * 4; eb < E; eb += stride) {
        int4 rv, cv;
        if (eb + 4 <= E) {
            rv = __ldg(reinterpret_cast<const int4*>(ei + eb));
            cv = __ldg(reinterpret_cast<const int4*>(ei + E + eb));
        } else {
            int* rp = &rv.x; int* cp = &cv.x;
            #pragma unroll
            for (int j = 0; j < 4; j++) {
                int e = eb + j < E ? eb + j : E - 1;
                rp[j] = __ldg(ei + e);
                cp[j] = __ldg(ei + E + e);
            }
        }
        const int* rp = &rv.x;
        const int* cp = &cv.x;

        uint4 av[4], bv[4];
        #pragma unroll
        for (int j = 0; j < 4; j++) {
            av[j] = __ldg(reinterpret_cast<const uint4*>(
                        g_H2 + (size_t)rp[j] * HOUT) + sub);
            bv[j] = __ldg(reinterpret_cast<const uint4*>(
                        g_H2 + (size_t)cp[j] * HOUT + HID) + sub);
        }

        float z[4];
        #pragma unroll
        for (int j = 0; j < 4; j++) {
            const __half2* ah = reinterpret_cast<const __half2*>(&av[j]);
            const __half2* bh = reinterpret_cast<const __half2*>(&bv[j]);
            float zz = 0.0f;
            #pragma unroll
            for (int q = 0; q < 4; q++) {
                __half2 s = __hmax2(__hadd2(ah[q], bh[q]),
                                    __half2(__half(0), __half(0)));
                float2 f = __half22float2(s);
                zz = fmaf(f.x, w2r[2 * q],     zz);
                zz = fmaf(f.y, w2r[2 * q + 1], zz);
            }
            z[j] = zz;
        }
        #pragma unroll
        for (int j = 0; j < 4; j++) {
            z[j] += __shfl_xor_sync(0xFFFFFFFF, z[j], 1);
            z[j] += __shfl_xor_sync(0xFFFFFFFF, z[j], 2);
            z[j] += __shfl_xor_sync(0xFFFFFFFF, z[j], 4);
        }
        if (sub == 0) {
            #pragma unroll
            for (int j = 0; j < 4; j++) {
                if (eb + j < E)
                    out[eb + j] = 1.0f / (1.0f + __expf(-(z[j] + bias2)));
            }
        }
    }
}

extern "C" void kernel_launch(void* const* d_in, const int* in_sizes, int n_in,
                              void* d_out, int out_size) {
    const float* x  = (const float*)d_in[0];
    const int*   ei = (const int*)  d_in[1];
    const float* W1 = (const float*)d_in[2];
    const float* b1 = (const float*)d_in[3];
    const float* W2 = (const float*)d_in[4];
    const float* b2 = (const float*)d_in[5];
    float* out = (float*)d_out;

    const int E = out_size;
    int n_nodes = in_sizes[0] / NODE_DIM;
    if (n_nodes > MAXN) n_nodes = MAXN;
    const int ntiles = (n_nodes + 127) / 128;

    cudaFuncSetAttribute(node_gemm,
                         cudaFuncAttributeMaxDynamicSharedMemorySize, SMEM_G);

    int g1 = ntiles < 148 ? ntiles : 148;
    node_gemm<<<g1, 256, SMEM_G>>>(x, W1, b1, n_nodes, ntiles);

    edge_eval<<<592, 256>>>(ei, W2, b2, out, E);
}